// round 12
// baseline (speedup 1.0000x reference)
#include <cuda_runtime.h>
#include <cuda_bf16.h>
#include <cstdint>

#define B_  32
#define CT  512
#define GC  128
#define H_  56
#define W_  56
#define HW  3136
#define FEATS_BASE (B_*GC*HW)   // 12,845,056 floats: mem section size

// Scratch (device-global; allocation inside kernel_launch is forbidden)
__device__ float g_q[B_*GC*HW];                 // q post elu+1, channel-major [b][c][n]
__device__ float g_kt[(long)B_*HW*GC];          // k post elu+1, px-major [b][px][c]
__device__ float g_kv[B_*4*32*32];              // kv accumulators per (b,h,d,e)
__device__ float g_ksum[B_*4*32];               // k column sums per (b,h,d)
__device__ __nv_bfloat16 g_xt[(long)B_*HW*256]; // [b][px][ Xhi(128) | Xlo(128) ] bf16
__device__ __nv_bfloat16 g_wh[256*128];         // W hi bf16, [o][k]
__device__ __nv_bfloat16 g_wl[256*128];         // W lo bf16, [o][k]

__device__ __forceinline__ uint32_t smem_to_u32(const void* p) {
    uint32_t a;
    asm("{ .reg .u64 t; cvta.to.shared.u64 t, %1; cvt.u32.u64 %0, t; }" : "=r"(a) : "l"(p));
    return a;
}

#define LDMATRIX_X4(r0, r1, r2, r3, addr) \
    asm volatile("ldmatrix.sync.aligned.m8n8.x4.shared.b16 {%0,%1,%2,%3}, [%4];" \
                 : "=r"(r0), "=r"(r1), "=r"(r2), "=r"(r3) : "r"(addr))

#define MMA_16816(c0, c1, c2, c3, a0, a1, a2, a3, b0, b1) \
    asm volatile("mma.sync.aligned.m16n8k16.row.col.f32.bf16.bf16.f32 " \
                 "{%0,%1,%2,%3}, {%4,%5,%6,%7}, {%8,%9}, {%0,%1,%2,%3};" \
                 : "+f"(c0), "+f"(c1), "+f"(c2), "+f"(c3) \
                 : "r"(a0), "r"(a1), "r"(a2), "r"(a3), "r"(b0), "r"(b1))

// ---------------------------------------------------------------------------
__global__ __launch_bounds__(256) void prep_kernel(const float* __restrict__ wqk) {
    int i = blockIdx.x * 256 + threadIdx.x;
    if (i < 256 * 128) {
        float w = wqk[i];
        __nv_bfloat16 h = __float2bfloat16_rn(w);
        g_wh[i] = h;
        g_wl[i] = __float2bfloat16_rn(w - __bfloat162float(h));
    }
    if (i < B_*4*32*32) g_kv[i] = 0.f;
    if (i < B_*4*32)    g_ksum[i] = 0.f;
}

// ---------------------------------------------------------------------------
__global__ void copy_mem_kernel(const float4* __restrict__ x, float4* __restrict__ out) {
    long i = (long)blockIdx.x * blockDim.x + threadIdx.x;
    const long total = (long)B_ * GC * HW / 4;
    if (i >= total) return;
    const int per_b = GC * HW / 4;
    int b = (int)(i / per_b);
    int r = (int)(i % per_b);
    out[i] = x[(long)b * (CT * HW / 4) + r];
}

// ---------------------------------------------------------------------------
// Transpose + split-bf16 convert: x[b][128+c][px] -> g_xt[b][px][ hi(128) | lo(128) ]
__global__ __launch_bounds__(256) void cvt_kernel(const float* __restrict__ x) {
    __shared__ float tile[32][33];
    int b = blockIdx.z;
    int ch0 = blockIdx.y * 32;
    int px0 = blockIdx.x * 32;
    int tid = threadIdx.x;
    int tx = tid & 31, ty = tid >> 5;

    const float* src = x + ((long)b * CT + GC + ch0) * HW + px0;
    #pragma unroll
    for (int r = 0; r < 4; r++) {
        int c = ty + r * 8;
        tile[c][tx] = src[(long)c * HW + tx];
    }
    __syncthreads();

    uint32_t* dstu = reinterpret_cast<uint32_t*>(g_xt);
    #pragma unroll
    for (int r = 0; r < 4; r++) {
        int pxl = ty + r * 8;
        long rowBase = ((long)b * HW + px0 + pxl) * 128;
        int pi = (tx < 16) ? tx : (tx - 16);
        float f0 = tile[2*pi][pxl];
        float f1 = tile[2*pi+1][pxl];
        __nv_bfloat16 h0 = __float2bfloat16_rn(f0);
        __nv_bfloat16 h1 = __float2bfloat16_rn(f1);
        uint32_t val;
        if (tx < 16) {
            val = (uint32_t)__bfloat16_as_ushort(h0) | ((uint32_t)__bfloat16_as_ushort(h1) << 16);
            dstu[rowBase + (ch0 >> 1) + pi] = val;
        } else {
            __nv_bfloat16 l0 = __float2bfloat16_rn(f0 - __bfloat162float(h0));
            __nv_bfloat16 l1 = __float2bfloat16_rn(f1 - __bfloat162float(h1));
            val = (uint32_t)__bfloat16_as_ushort(l0) | ((uint32_t)__bfloat16_as_ushort(l1) << 16);
            dstu[rowBase + 64 + (ch0 >> 1) + pi] = val;
        }
    }
}

// ---------------------------------------------------------------------------
// qk GEMM via mma.sync split-bf16. Block: 128 o x 128 px, 8 warps (32o x 64n).
// A via ldmatrix from smem-staged W chunks; B staged from g_xt.
#define BS_STRIDE 264
#define WC_STRIDE 24
#define SM_BS     0
#define SM_WC     (128 * BS_STRIDE * 2)      // 67584
#define WC_HALF   (128 * WC_STRIDE * 2)      // 6144
#define SM_TOTAL  (SM_WC + 2 * WC_HALF)      // 79872
#define DS_STR    132

__global__ __launch_bounds__(256, 2) void qk_mma_kernel(const float* __restrict__ bqk) {
    extern __shared__ __align__(16) char sm[];
    __nv_bfloat16* Bs = (__nv_bfloat16*)(sm + SM_BS);
    float* Ds = (float*)sm;   // union; used after compute

    int b = blockIdx.z;
    int oBase = blockIdx.y * 128;
    int pBase = blockIdx.x * 128;
    int tid = threadIdx.x;
    int wid = tid >> 5, lane = tid & 31;
    int oSub = (wid & 3) * 32;
    int nSub = (wid >> 2) * 64;

    // ---- load B tile: 128 px rows x 256 bf16 (hi|lo), guarded
    {
        const uint4* src = (const uint4*)(g_xt + ((long)b * HW + pBase) * 256);
        const uint4 z4 = make_uint4(0u, 0u, 0u, 0u);
        #pragma unroll
        for (int it = 0; it < 16; it++) {
            int idx = tid + it * 256;
            int row = idx >> 5;
            int j = idx & 31;
            uint4 v = (pBase + row < HW) ? src[row * 32 + j] : z4;
            *(uint4*)(Bs + row * BS_STRIDE + j * 8) = v;
        }
    }

    float acc[2][8][4];
    #pragma unroll
    for (int mt = 0; mt < 2; mt++)
        #pragma unroll
        for (int nt = 0; nt < 8; nt++)
            #pragma unroll
            for (int c = 0; c < 4; c++) acc[mt][nt][c] = 0.f;

    int wrow = tid >> 1, wseg = tid & 1;
    const uint4* ghp = (const uint4*)(g_wh + (long)(oBase + wrow) * 128 + wseg * 8);
    const uint4* glp = (const uint4*)(g_wl + (long)(oBase + wrow) * 128 + wseg * 8);
    uint4* sh = (uint4*)(sm + SM_WC + wrow * (WC_STRIDE * 2) + wseg * 16);
    uint4* sl = (uint4*)(sm + SM_WC + WC_HALF + wrow * (WC_STRIDE * 2) + wseg * 16);

    uint32_t aOff = (uint32_t)((oSub + (lane & 15)) * (WC_STRIDE * 2) + (lane >> 4) * 16);
    uint32_t aAddrH = smem_to_u32(sm + SM_WC) + aOff;
    uint32_t aAddrL = aAddrH + WC_HALF;

    uint32_t g = (uint32_t)(lane >> 3);
    uint32_t bRow = (uint32_t)(nSub + ((g >> 1) << 3) + (lane & 7));
    uint32_t bAddr0 = smem_to_u32(Bs) + bRow * (BS_STRIDE * 2) + (g & 1) * 16;

    uint4 ph = ghp[0];
    uint4 pl = glp[0];

    #pragma unroll
    for (int ks = 0; ks < 8; ks++) {
        __syncthreads();
        *sh = ph;
        *sl = pl;
        __syncthreads();
        if (ks < 7) {
            ph = ghp[(ks + 1) * 2];
            pl = glp[(ks + 1) * 2];
        }

        uint32_t aH[2][4], aL[2][4];
        #pragma unroll
        for (int mt = 0; mt < 2; mt++) {
            LDMATRIX_X4(aH[mt][0], aH[mt][1], aH[mt][2], aH[mt][3],
                        aAddrH + (uint32_t)(mt * 16 * (WC_STRIDE * 2)));
            LDMATRIX_X4(aL[mt][0], aL[mt][1], aL[mt][2], aL[mt][3],
                        aAddrL + (uint32_t)(mt * 16 * (WC_STRIDE * 2)));
        }
        int kc = ks * 16;
        uint32_t bkbH = (uint32_t)(kc * 2);
        uint32_t bkbL = (uint32_t)((128 + kc) * 2);

        #pragma unroll
        for (int m = 0; m < 4; m++) {
            uint32_t bOff = bAddr0 + (uint32_t)(m * 16 * (BS_STRIDE * 2));
            uint32_t hF[4], lF[4];
            LDMATRIX_X4(hF[0], hF[1], hF[2], hF[3], bOff + bkbH);
            LDMATRIX_X4(lF[0], lF[1], lF[2], lF[3], bOff + bkbL);
            #pragma unroll
            for (int sub = 0; sub < 2; sub++) {
                int nt = m * 2 + sub;
                uint32_t bh0 = hF[sub * 2], bh1 = hF[sub * 2 + 1];
                uint32_t bl0 = lF[sub * 2], bl1 = lF[sub * 2 + 1];
                #pragma unroll
                for (int mt = 0; mt < 2; mt++) {
                    MMA_16816(acc[mt][nt][0], acc[mt][nt][1], acc[mt][nt][2], acc[mt][nt][3],
                              aH[mt][0], aH[mt][1], aH[mt][2], aH[mt][3], bh0, bh1);
                    MMA_16816(acc[mt][nt][0], acc[mt][nt][1], acc[mt][nt][2], acc[mt][nt][3],
                              aH[mt][0], aH[mt][1], aH[mt][2], aH[mt][3], bl0, bl1);
                    MMA_16816(acc[mt][nt][0], acc[mt][nt][1], acc[mt][nt][2], acc[mt][nt][3],
                              aL[mt][0], aL[mt][1], aL[mt][2], aL[mt][3], bh0, bh1);
                }
            }
        }
    }
    __syncthreads();   // done with Bs/Wc; alias as Ds

    if (blockIdx.y == 0) {
        // ---- q epilogue: Ds[o][n] stride 132, channel-major coalesced store
        #pragma unroll
        for (int mt = 0; mt < 2; mt++) {
            #pragma unroll
            for (int half = 0; half < 2; half++) {
                int row = oSub + mt * 16 + (lane >> 2) + half * 8;
                float bias = bqk[row];
                #pragma unroll
                for (int nt = 0; nt < 8; nt++) {
                    int col = nSub + nt * 8 + (lane & 3) * 2;
                    float v0 = acc[mt][nt][half * 2 + 0] + bias;
                    float v1 = acc[mt][nt][half * 2 + 1] + bias;
                    Ds[row * DS_STR + col]     = (v0 > 0.f) ? (v0 + 1.f) : __expf(v0);
                    Ds[row * DS_STR + col + 1] = (v1 > 0.f) ? (v1 + 1.f) : __expf(v1);
                }
            }
        }
        __syncthreads();
        float* base = g_q + (long)b * GC * HW + pBase;
        #pragma unroll
        for (int it = 0; it < 16; it++) {
            int idx = tid + it * 256;
            int o = idx >> 5, c4 = idx & 31;
            if (pBase + c4 * 4 < HW) {
                float4 v = *(float4*)(Ds + o * DS_STR + c4 * 4);
                *(float4*)(base + (long)o * HW + c4 * 4) = v;
            }
        }
    } else {
        // ---- k epilogue: Ds[n][o] stride 132, px-major coalesced store
        #pragma unroll
        for (int mt = 0; mt < 2; mt++) {
            #pragma unroll
            for (int half = 0; half < 2; half++) {
                int row = oSub + mt * 16 + (lane >> 2) + half * 8;
                float bias = bqk[GC + row];
                #pragma unroll
                for (int nt = 0; nt < 8; nt++) {
                    int col = nSub + nt * 8 + (lane & 3) * 2;
                    float v0 = acc[mt][nt][half * 2 + 0] + bias;
                    float v1 = acc[mt][nt][half * 2 + 1] + bias;
                    Ds[col * DS_STR + row]       = (v0 > 0.f) ? (v0 + 1.f) : __expf(v0);
                    Ds[(col + 1) * DS_STR + row] = (v1 > 0.f) ? (v1 + 1.f) : __expf(v1);
                }
            }
        }
        __syncthreads();
        float* base = g_kt + ((long)b * HW + pBase) * GC;
        #pragma unroll
        for (int it = 0; it < 16; it++) {
            int idx = tid + it * 256;
            int n = idx >> 5, c4 = idx & 31;
            if (pBase + n < HW) {
                float4 v = *(float4*)(Ds + n * DS_STR + c4 * 4);
                *(float4*)(base + (long)n * GC + c4 * 4) = v;
            }
        }
    }
}

// ---------------------------------------------------------------------------
// kv[b,h,d,e] += sum_n k[d,n]*v[e,n] ; ksum[b,h,d] += sum_n k[d,n]
// K staged px-major (float4 LDS), V transpose-loaded px-major.
__global__ __launch_bounds__(256) void kv_reduce_kernel(const float* __restrict__ x) {
    __shared__ float Ks[128][36];
    __shared__ float Vs[128][36];
    __shared__ float ksp[4][8][4];
    int b = blockIdx.z, h = blockIdx.y;
    int p0 = blockIdx.x * 128;
    int tid = threadIdx.x;

    const float* Kt = g_kt + (long)b * HW * GC + h * 32;
    #pragma unroll
    for (int it = 0; it < 4; it++) {
        int idx = tid + it * 256;
        int p = idx >> 3, d4 = idx & 7;
        float4 v = make_float4(0.f, 0.f, 0.f, 0.f);
        if (p0 + p < HW) v = *(const float4*)(Kt + (long)(p0 + p) * GC + d4 * 4);
        *(float4*)&Ks[p][d4 * 4] = v;
    }
    const float* Vb = x + ((long)b * CT + GC + h * 32) * HW;
    for (int idx = tid; idx < 4096; idx += 256) {
        int d = idx >> 7, p = idx & 127;
        Vs[p][d] = (p0 + p < HW) ? Vb[(long)d * HW + p0 + p] : 0.f;
    }
    __syncthreads();

    int tt = tid & 63, ng = tid >> 6;
    int d0 = (tt >> 3) * 4;
    int e0 = (tt & 7) * 4;
    bool doKs = (e0 == 0);

    float acc[4][4];
    float ks[4] = {0.f, 0.f, 0.f, 0.f};
    #pragma unroll
    for (int i = 0; i < 4; i++)
        #pragma unroll
        for (int j = 0; j < 4; j++) acc[i][j] = 0.f;

    int nb = ng * 32;
    #pragma unroll 8
    for (int n = 0; n < 32; n++) {
        int p = nb + n;
        float4 kr = *(const float4*)&Ks[p][d0];
        float4 vr = *(const float4*)&Vs[p][e0];
        float krv[4] = {kr.x, kr.y, kr.z, kr.w};
        float vrv[4] = {vr.x, vr.y, vr.z, vr.w};
        #pragma unroll
        for (int i = 0; i < 4; i++)
            #pragma unroll
            for (int j = 0; j < 4; j++) acc[i][j] += krv[i] * vrv[j];
        if (doKs) {
            #pragma unroll
            for (int i = 0; i < 4; i++) ks[i] += krv[i];
        }
    }
    if (doKs) {
        #pragma unroll
        for (int i = 0; i < 4; i++) ksp[ng][tt >> 3][i] = ks[i];
    }
    __syncthreads();
    float* part = &Ks[0][0];
    #pragma unroll
    for (int i = 0; i < 4; i++)
        #pragma unroll
        for (int j = 0; j < 4; j++) part[(ng * 64 + tt) * 16 + i * 4 + j] = acc[i][j];
    __syncthreads();

    if (tid < 64) {
        float r[16];
        #pragma unroll
        for (int v = 0; v < 16; v++)
            r[v] = part[tid * 16 + v] + part[(64 + tid) * 16 + v]
                 + part[(128 + tid) * 16 + v] + part[(192 + tid) * 16 + v];
        int dd0 = (tid >> 3) * 4, ee0 = (tid & 7) * 4;
        float* kvdst = g_kv + (((long)(b * 4 + h) * 32 + dd0) * 32 + ee0);
        #pragma unroll
        for (int i = 0; i < 4; i++)
            #pragma unroll
            for (int j = 0; j < 4; j++) atomicAdd(kvdst + i * 32 + j, r[i * 4 + j]);
    }
    if (tid < 32) {
        float s = ksp[0][tid >> 2][tid & 3] + ksp[1][tid >> 2][tid & 3]
                + ksp[2][tid >> 2][tid & 3] + ksp[3][tid >> 2][tid & 3];
        atomicAdd(g_ksum + (b * 4 + h) * 32 + tid, s);
    }
}

// ---------------------------------------------------------------------------
// att: q read channel-major (lane-coalesced over n).
__global__ __launch_bounds__(256) void att_kernel(float* __restrict__ out) {
    __shared__ float4 kvs4[1024];
    __shared__ float  kms[128];
    int b = blockIdx.y;
    int p0 = blockIdx.x * 128;
    int tid = threadIdx.x;
    const float invHW = 1.f / (float)HW;
    const float4* kvsrc = (const float4*)(g_kv + (long)b * 4096);
    for (int idx = tid; idx < 1024; idx += 256) {
        float4 v = kvsrc[idx];
        v.x *= invHW; v.y *= invHW; v.z *= invHW; v.w *= invHW;
        kvs4[idx] = v;
    }
    if (tid < 128) kms[tid] = g_ksum[b * 128 + tid] * invHW;
    __syncthreads();

    int h = tid >> 6, lp = tid & 63;
    int n1 = p0 + lp, n2 = p0 + 64 + lp;
    bool v1 = n1 < HW, v2 = n2 < HW;
    const float* qb = g_q + ((long)b * GC + h * 32) * HW;

    float q1[32], q2[32];
    #pragma unroll
    for (int d = 0; d < 32; d++) {
        q1[d] = v1 ? qb[(long)d * HW + n1] : 0.f;
        q2[d] = v2 ? qb[(long)d * HW + n2] : 0.f;
    }
    float s1 = 0.f, s2 = 0.f;
    #pragma unroll
    for (int d = 0; d < 32; d++) {
        float km = kms[h * 32 + d];
        s1 += q1[d] * km;
        s2 += q2[d] * km;
    }
    float z1 = 1.f / (s1 + 1e-6f);
    float z2 = 1.f / (s2 + 1e-6f);

    float* ob = out + FEATS_BASE + ((long)b * 384 + h * 32) * HW;
    #pragma unroll
    for (int e4 = 0; e4 < 8; e4++) {
        float4 a1 = make_float4(0,0,0,0), a2 = make_float4(0,0,0,0);
        #pragma unroll
        for (int d = 0; d < 32; d++) {
            float4 kv = kvs4[(h * 32 + d) * 8 + e4];
            a1.x += q1[d] * kv.x; a1.y += q1[d] * kv.y;
            a1.z += q1[d] * kv.z; a1.w += q1[d] * kv.w;
            a2.x += q2[d] * kv.x; a2.y += q2[d] * kv.y;
            a2.z += q2[d] * kv.z; a2.w += q2[d] * kv.w;
        }
        int e = e4 * 4;
        if (v1) {
            ob[(long)(e+0) * HW + n1] = a1.x * z1;
            ob[(long)(e+1) * HW + n1] = a1.y * z1;
            ob[(long)(e+2) * HW + n1] = a1.z * z1;
            ob[(long)(e+3) * HW + n1] = a1.w * z1;
        }
        if (v2) {
            ob[(long)(e+0) * HW + n2] = a2.x * z2;
            ob[(long)(e+1) * HW + n2] = a2.y * z2;
            ob[(long)(e+2) * HW + n2] = a2.z * z2;
            ob[(long)(e+3) * HW + n2] = a2.w * z2;
        }
    }
}

// ---------------------------------------------------------------------------
__global__ __launch_bounds__(112) void dw3_kernel(const float* __restrict__ x,
                                                  const float* __restrict__ w,
                                                  const float* __restrict__ bias,
                                                  float* __restrict__ out) {
    __shared__ float tile[10][60];
    __shared__ float ws[9];
    int y0 = blockIdx.x * 8;
    int c = blockIdx.y, b = blockIdx.z;
    int tid = threadIdx.x;
    const float* in = x + ((long)b * CT + 2 * GC + c) * HW;

    if (tid < 9) ws[tid] = w[c * 9 + tid];
    for (int idx = tid; idx < 10 * 58; idx += 112) {
        int r = idx / 58, cc = idx % 58;
        int iy = y0 - 1 + r, ix = cc - 1;
        tile[r][cc] = (iy >= 0 && iy < H_ && ix >= 0 && ix < W_) ? in[iy * W_ + ix] : 0.f;
    }
    __syncthreads();

    int gx = tid % 14, gy = tid / 14;
    int xb = gx * 4;
    float bb = bias[c];
    float a0 = bb, a1 = bb, a2 = bb, a3 = bb;
    #pragma unroll
    for (int ky = 0; ky < 3; ky++) {
        const float* row = &tile[gy + ky][xb];
        float r[6];
        #pragma unroll
        for (int i = 0; i < 6; i++) r[i] = row[i];
        #pragma unroll
        for (int kx = 0; kx < 3; kx++) {
            float wv = ws[ky * 3 + kx];
            a0 += wv * r[kx + 0];
            a1 += wv * r[kx + 1];
            a2 += wv * r[kx + 2];
            a3 += wv * r[kx + 3];
        }
    }
    float* ob = out + FEATS_BASE + ((long)b * 384 + GC + c) * HW + (y0 + gy) * W_ + xb;
    ob[0] = a0; ob[1] = a1; ob[2] = a2; ob[3] = a3;
}

// ---------------------------------------------------------------------------
__global__ __launch_bounds__(112) void dw7_kernel(const float* __restrict__ x,
                                                  const float* __restrict__ w,
                                                  const float* __restrict__ bias,
                                                  float* __restrict__ out) {
    __shared__ float tile[14][64];
    __shared__ float ws[49];
    int y0 = blockIdx.x * 8;
    int c = blockIdx.y, b = blockIdx.z;
    int tid = threadIdx.x;
    const float* in = x + ((long)b * CT + 3 * GC + c) * HW;

    if (tid < 49) ws[tid] = w[c * 49 + tid];
    for (int idx = tid; idx < 14 * 62; idx += 112) {
        int r = idx / 62, cc = idx % 62;
        int iy = y0 - 3 + r, ix = cc - 3;
        tile[r][cc] = (iy >= 0 && iy < H_ && ix >= 0 && ix < W_) ? in[iy * W_ + ix] : 0.f;
    }
    __syncthreads();

    int gx = tid % 14, gy = tid / 14;
    int xb = gx * 4;
    float bb = bias[c];
    float a0 = bb, a1 = bb, a2 = bb, a3 = bb;
    #pragma unroll
    for (int ky = 0; ky < 7; ky++) {
        const float* row = &tile[gy + ky][xb];
        float r[10];
        #pragma unroll
        for (int i = 0; i < 10; i++) r[i] = row[i];
        #pragma unroll
        for (int kx = 0; kx < 7; kx++) {
            float wv = ws[ky * 7 + kx];
            a0 += wv * r[kx + 0];
            a1 += wv * r[kx + 1];
            a2 += wv * r[kx + 2];
            a3 += wv * r[kx + 3];
        }
    }
    float* ob = out + FEATS_BASE + ((long)b * 384 + 2 * GC + c) * HW + (y0 + gy) * W_ + xb;
    ob[0] = a0; ob[1] = a1; ob[2] = a2; ob[3] = a3;
}

// ---------------------------------------------------------------------------
extern "C" void kernel_launch(void* const* d_in, const int* in_sizes, int n_in,
                              void* d_out, int out_size) {
    const float* x     = (const float*)d_in[0];
    const float* w_dw1 = (const float*)d_in[1];
    const float* b_dw1 = (const float*)d_in[2];
    const float* w_dw2 = (const float*)d_in[3];
    const float* b_dw2 = (const float*)d_in[4];
    const float* w_qk  = (const float*)d_in[5];
    const float* b_qk  = (const float*)d_in[6];
    float* out = (float*)d_out;

    cudaFuncSetAttribute(qk_mma_kernel, cudaFuncAttributeMaxDynamicSharedMemorySize, SM_TOTAL);

    // NOTE: kv_reduce at launch index 3 so ncu (-s/-c window) profiles it.
    prep_kernel<<<512, 256>>>(w_qk);
    cvt_kernel<<<dim3(98, 4, B_), 256>>>(x);
    qk_mma_kernel<<<dim3(25, 2, B_), 256, SM_TOTAL>>>(b_qk);
    kv_reduce_kernel<<<dim3(25, 4, B_), 256>>>(x);
    att_kernel<<<dim3(25, B_), 256>>>(out);
    copy_mem_kernel<<<(B_ * GC * HW / 4 + 255) / 256, 256>>>((const float4*)x, (float4*)out);
    dw3_kernel<<<dim3(7, GC, B_), 112>>>(x, w_dw1, b_dw1, out);
    dw7_kernel<<<dim3(7, GC, B_), 112>>>(x, w_dw2, b_dw2, out);
}

// round 13
// speedup vs baseline: 1.1173x; 1.1173x over previous
#include <cuda_runtime.h>
#include <cuda_bf16.h>
#include <cstdint>

#define B_  32
#define CT  512
#define GC  128
#define H_  56
#define W_  56
#define HW  3136
#define FEATS_BASE (B_*GC*HW)   // 12,845,056 floats: mem section size

// Scratch (device-global; allocation inside kernel_launch is forbidden)
__device__ float g_q[B_*GC*HW];                 // q post elu+1, channel-major [b][c][n]
__device__ float g_kv[B_*4*32*32];              // kv accumulators per (b,h,d,e)
__device__ float g_ksum[B_*4*32];               // k column sums per (b,h,d)
__device__ __nv_bfloat16 g_xt[(long)B_*HW*256]; // [b][px][ Xhi(128) | Xlo(128) ] bf16
__device__ __nv_bfloat16 g_wh[256*128];         // W hi bf16, [o][k]
__device__ __nv_bfloat16 g_wl[256*128];         // W lo bf16, [o][k]

__device__ __forceinline__ uint32_t smem_to_u32(const void* p) {
    uint32_t a;
    asm("{ .reg .u64 t; cvta.to.shared.u64 t, %1; cvt.u32.u64 %0, t; }" : "=r"(a) : "l"(p));
    return a;
}

#define LDMATRIX_X4(r0, r1, r2, r3, addr) \
    asm volatile("ldmatrix.sync.aligned.m8n8.x4.shared.b16 {%0,%1,%2,%3}, [%4];" \
                 : "=r"(r0), "=r"(r1), "=r"(r2), "=r"(r3) : "r"(addr))

#define MMA_16816(c0, c1, c2, c3, a0, a1, a2, a3, b0, b1) \
    asm volatile("mma.sync.aligned.m16n8k16.row.col.f32.bf16.bf16.f32 " \
                 "{%0,%1,%2,%3}, {%4,%5,%6,%7}, {%8,%9}, {%0,%1,%2,%3};" \
                 : "+f"(c0), "+f"(c1), "+f"(c2), "+f"(c3) \
                 : "r"(a0), "r"(a1), "r"(a2), "r"(a3), "r"(b0), "r"(b1))

// ---------------------------------------------------------------------------
__global__ __launch_bounds__(256) void prep_kernel(const float* __restrict__ wqk) {
    int i = blockIdx.x * 256 + threadIdx.x;
    if (i < 256 * 128) {
        float w = wqk[i];
        __nv_bfloat16 h = __float2bfloat16_rn(w);
        g_wh[i] = h;
        g_wl[i] = __float2bfloat16_rn(w - __bfloat162float(h));
    }
    if (i < B_*4*32*32) g_kv[i] = 0.f;
    if (i < B_*4*32)    g_ksum[i] = 0.f;
}

// ---------------------------------------------------------------------------
__global__ void copy_mem_kernel(const float4* __restrict__ x, float4* __restrict__ out) {
    long i = (long)blockIdx.x * blockDim.x + threadIdx.x;
    const long total = (long)B_ * GC * HW / 4;
    if (i >= total) return;
    const int per_b = GC * HW / 4;
    int b = (int)(i / per_b);
    int r = (int)(i % per_b);
    out[i] = x[(long)b * (CT * HW / 4) + r];
}

// ---------------------------------------------------------------------------
// Transpose + split-bf16 convert: x[b][128+c][px] -> g_xt[b][px][ hi(128) | lo(128) ]
__global__ __launch_bounds__(256) void cvt_kernel(const float* __restrict__ x) {
    __shared__ float tile[32][33];
    int b = blockIdx.z;
    int ch0 = blockIdx.y * 32;
    int px0 = blockIdx.x * 32;
    int tid = threadIdx.x;
    int tx = tid & 31, ty = tid >> 5;

    const float* src = x + ((long)b * CT + GC + ch0) * HW + px0;
    #pragma unroll
    for (int r = 0; r < 4; r++) {
        int c = ty + r * 8;
        tile[c][tx] = src[(long)c * HW + tx];
    }
    __syncthreads();

    uint32_t* dstu = reinterpret_cast<uint32_t*>(g_xt);
    #pragma unroll
    for (int r = 0; r < 4; r++) {
        int pxl = ty + r * 8;
        long rowBase = ((long)b * HW + px0 + pxl) * 128;
        int pi = (tx < 16) ? tx : (tx - 16);
        float f0 = tile[2*pi][pxl];
        float f1 = tile[2*pi+1][pxl];
        __nv_bfloat16 h0 = __float2bfloat16_rn(f0);
        __nv_bfloat16 h1 = __float2bfloat16_rn(f1);
        uint32_t val;
        if (tx < 16) {
            val = (uint32_t)__bfloat16_as_ushort(h0) | ((uint32_t)__bfloat16_as_ushort(h1) << 16);
            dstu[rowBase + (ch0 >> 1) + pi] = val;
        } else {
            __nv_bfloat16 l0 = __float2bfloat16_rn(f0 - __bfloat162float(h0));
            __nv_bfloat16 l1 = __float2bfloat16_rn(f1 - __bfloat162float(h1));
            val = (uint32_t)__bfloat16_as_ushort(l0) | ((uint32_t)__bfloat16_as_ushort(l1) << 16);
            dstu[rowBase + 64 + (ch0 >> 1) + pi] = val;
        }
    }
}

// ---------------------------------------------------------------------------
// qk GEMM via mma.sync split-bf16. Block: 128 o x 128 px, 8 warps (32o x 64n).
// q branch: store channel-major. k branch: keep k in smem, fuse kv/ksum
// reduction (V staged 64ch at a time), atomics into g_kv/g_ksum. No k stores.
#define BS_STRIDE 264
#define WC_STRIDE 24
#define SM_BS     0
#define SM_WC     (128 * BS_STRIDE * 2)      // 67584
#define WC_HALF   (128 * WC_STRIDE * 2)      // 6144
#define SM_VS     67584                      // V staging (after Ds region)
#define VS_STR    68
#define SM_TOTAL  (SM_VS + 128 * VS_STR * 4) // 102400
#define DS_STR    132

__global__ __launch_bounds__(256, 2) void qk_mma_kernel(const float* __restrict__ x,
                                                        const float* __restrict__ bqk) {
    extern __shared__ __align__(16) char sm[];
    __nv_bfloat16* Bs = (__nv_bfloat16*)(sm + SM_BS);
    float* Ds = (float*)sm;                 // union; used after compute
    float* Vs = (float*)(sm + SM_VS);       // k-branch V staging

    int b = blockIdx.z;
    int oBase = blockIdx.y * 128;
    int pBase = blockIdx.x * 128;
    int tid = threadIdx.x;
    int wid = tid >> 5, lane = tid & 31;
    int oSub = (wid & 3) * 32;
    int nSub = (wid >> 2) * 64;

    // ---- load B tile: 128 px rows x 256 bf16 (hi|lo), guarded
    {
        const uint4* src = (const uint4*)(g_xt + ((long)b * HW + pBase) * 256);
        const uint4 z4 = make_uint4(0u, 0u, 0u, 0u);
        #pragma unroll
        for (int it = 0; it < 16; it++) {
            int idx = tid + it * 256;
            int row = idx >> 5;
            int j = idx & 31;
            uint4 v = (pBase + row < HW) ? src[row * 32 + j] : z4;
            *(uint4*)(Bs + row * BS_STRIDE + j * 8) = v;
        }
    }

    float acc[2][8][4];
    #pragma unroll
    for (int mt = 0; mt < 2; mt++)
        #pragma unroll
        for (int nt = 0; nt < 8; nt++)
            #pragma unroll
            for (int c = 0; c < 4; c++) acc[mt][nt][c] = 0.f;

    int wrow = tid >> 1, wseg = tid & 1;
    const uint4* ghp = (const uint4*)(g_wh + (long)(oBase + wrow) * 128 + wseg * 8);
    const uint4* glp = (const uint4*)(g_wl + (long)(oBase + wrow) * 128 + wseg * 8);
    uint4* sh = (uint4*)(sm + SM_WC + wrow * (WC_STRIDE * 2) + wseg * 16);
    uint4* sl = (uint4*)(sm + SM_WC + WC_HALF + wrow * (WC_STRIDE * 2) + wseg * 16);

    uint32_t aOff = (uint32_t)((oSub + (lane & 15)) * (WC_STRIDE * 2) + (lane >> 4) * 16);
    uint32_t aAddrH = smem_to_u32(sm + SM_WC) + aOff;
    uint32_t aAddrL = aAddrH + WC_HALF;

    uint32_t g = (uint32_t)(lane >> 3);
    uint32_t bRow = (uint32_t)(nSub + ((g >> 1) << 3) + (lane & 7));
    uint32_t bAddr0 = smem_to_u32(Bs) + bRow * (BS_STRIDE * 2) + (g & 1) * 16;

    uint4 ph = ghp[0];
    uint4 pl = glp[0];

    #pragma unroll
    for (int ks = 0; ks < 8; ks++) {
        __syncthreads();
        *sh = ph;
        *sl = pl;
        __syncthreads();
        if (ks < 7) {
            ph = ghp[(ks + 1) * 2];
            pl = glp[(ks + 1) * 2];
        }

        uint32_t aH[2][4], aL[2][4];
        #pragma unroll
        for (int mt = 0; mt < 2; mt++) {
            LDMATRIX_X4(aH[mt][0], aH[mt][1], aH[mt][2], aH[mt][3],
                        aAddrH + (uint32_t)(mt * 16 * (WC_STRIDE * 2)));
            LDMATRIX_X4(aL[mt][0], aL[mt][1], aL[mt][2], aL[mt][3],
                        aAddrL + (uint32_t)(mt * 16 * (WC_STRIDE * 2)));
        }
        int kc = ks * 16;
        uint32_t bkbH = (uint32_t)(kc * 2);
        uint32_t bkbL = (uint32_t)((128 + kc) * 2);

        #pragma unroll
        for (int m = 0; m < 4; m++) {
            uint32_t bOff = bAddr0 + (uint32_t)(m * 16 * (BS_STRIDE * 2));
            uint32_t hF[4], lF[4];
            LDMATRIX_X4(hF[0], hF[1], hF[2], hF[3], bOff + bkbH);
            LDMATRIX_X4(lF[0], lF[1], lF[2], lF[3], bOff + bkbL);
            #pragma unroll
            for (int sub = 0; sub < 2; sub++) {
                int nt = m * 2 + sub;
                uint32_t bh0 = hF[sub * 2], bh1 = hF[sub * 2 + 1];
                uint32_t bl0 = lF[sub * 2], bl1 = lF[sub * 2 + 1];
                #pragma unroll
                for (int mt = 0; mt < 2; mt++) {
                    MMA_16816(acc[mt][nt][0], acc[mt][nt][1], acc[mt][nt][2], acc[mt][nt][3],
                              aH[mt][0], aH[mt][1], aH[mt][2], aH[mt][3], bh0, bh1);
                    MMA_16816(acc[mt][nt][0], acc[mt][nt][1], acc[mt][nt][2], acc[mt][nt][3],
                              aH[mt][0], aH[mt][1], aH[mt][2], aH[mt][3], bl0, bl1);
                    MMA_16816(acc[mt][nt][0], acc[mt][nt][1], acc[mt][nt][2], acc[mt][nt][3],
                              aL[mt][0], aL[mt][1], aL[mt][2], aL[mt][3], bh0, bh1);
                }
            }
        }
    }
    __syncthreads();   // done with Bs/Wc; alias as Ds

    if (blockIdx.y == 0) {
        // ---- q epilogue: Ds[o][n] stride 132, channel-major coalesced store
        #pragma unroll
        for (int mt = 0; mt < 2; mt++) {
            #pragma unroll
            for (int half = 0; half < 2; half++) {
                int row = oSub + mt * 16 + (lane >> 2) + half * 8;
                float bias = bqk[row];
                #pragma unroll
                for (int nt = 0; nt < 8; nt++) {
                    int col = nSub + nt * 8 + (lane & 3) * 2;
                    float v0 = acc[mt][nt][half * 2 + 0] + bias;
                    float v1 = acc[mt][nt][half * 2 + 1] + bias;
                    Ds[row * DS_STR + col]     = (v0 > 0.f) ? (v0 + 1.f) : __expf(v0);
                    Ds[row * DS_STR + col + 1] = (v1 > 0.f) ? (v1 + 1.f) : __expf(v1);
                }
            }
        }
        __syncthreads();
        float* base = g_q + (long)b * GC * HW + pBase;
        #pragma unroll
        for (int it = 0; it < 16; it++) {
            int idx = tid + it * 256;
            int o = idx >> 5, c4 = idx & 31;
            if (pBase + c4 * 4 < HW) {
                float4 v = *(float4*)(Ds + o * DS_STR + c4 * 4);
                *(float4*)(base + (long)o * HW + c4 * 4) = v;
            }
        }
    } else {
        // ---- k epilogue: Ds[px][c] (zeroed for invalid px), then fused
        //      kv/ksum reduction with V staged 64 channels at a time.
        #pragma unroll
        for (int mt = 0; mt < 2; mt++) {
            #pragma unroll
            for (int half = 0; half < 2; half++) {
                int row = oSub + mt * 16 + (lane >> 2) + half * 8;
                float bias = bqk[GC + row];
                #pragma unroll
                for (int nt = 0; nt < 8; nt++) {
                    int col = nSub + nt * 8 + (lane & 3) * 2;
                    bool ok = (pBase + col) < HW;   // col,col+1 same validity (boundary even)
                    float v0 = acc[mt][nt][half * 2 + 0] + bias;
                    float v1 = acc[mt][nt][half * 2 + 1] + bias;
                    v0 = (v0 > 0.f) ? (v0 + 1.f) : __expf(v0);
                    v1 = (v1 > 0.f) ? (v1 + 1.f) : __expf(v1);
                    Ds[col * DS_STR + row]       = ok ? v0 : 0.f;
                    Ds[(col + 1) * DS_STR + row] = ok ? v1 : 0.f;
                }
            }
        }

        int hh = tid >> 7;              // head within pair
        int t2 = tid & 127;
        int d0 = (t2 >> 3) * 2;         // 0,2,..,30
        int e0 = (t2 & 7) * 4;          // 0,4,..,28
        bool doKs = (e0 == 0);

        #pragma unroll
        for (int half = 0; half < 2; half++) {
            __syncthreads();            // Ds ready (half 0) / Vs free (half 1)
            // stage V channels [half*64, half*64+64)
            const float* Vb = x + ((long)b * CT + GC + half * 64) * HW;
            #pragma unroll
            for (int it = 0; it < 32; it++) {
                int idx = tid + it * 256;       // 8192 = 64c x 128p
                int c = idx >> 7, p = idx & 127;
                Vs[p * VS_STR + c] = (pBase + p < HW) ? Vb[(long)c * HW + pBase + p] : 0.f;
            }
            __syncthreads();

            int head = half * 2 + hh;
            const float* Dk = Ds + head * 32 + d0;
            const float* Vv = Vs + hh * 32 + e0;
            float a0[4] = {0,0,0,0}, a1[4] = {0,0,0,0};
            float ks0 = 0.f, ks1 = 0.f;
            #pragma unroll 8
            for (int p = 0; p < 128; p++) {
                float2 k2 = *(const float2*)(Dk + p * DS_STR);
                float4 v4 = *(const float4*)(Vv + p * VS_STR);
                a0[0] += k2.x * v4.x; a0[1] += k2.x * v4.y;
                a0[2] += k2.x * v4.z; a0[3] += k2.x * v4.w;
                a1[0] += k2.y * v4.x; a1[1] += k2.y * v4.y;
                a1[2] += k2.y * v4.z; a1[3] += k2.y * v4.w;
                if (doKs) { ks0 += k2.x; ks1 += k2.y; }
            }
            float* kvdst = g_kv + (((long)(b * 4 + head) * 32 + d0) * 32 + e0);
            #pragma unroll
            for (int j = 0; j < 4; j++) {
                atomicAdd(kvdst + j, a0[j]);
                atomicAdd(kvdst + 32 + j, a1[j]);
            }
            if (doKs) {
                atomicAdd(g_ksum + (b * 4 + head) * 32 + d0,     ks0);
                atomicAdd(g_ksum + (b * 4 + head) * 32 + d0 + 1, ks1);
            }
        }
    }
}

// ---------------------------------------------------------------------------
// att: q read channel-major (lane-coalesced over n).
__global__ __launch_bounds__(256) void att_kernel(float* __restrict__ out) {
    __shared__ float4 kvs4[1024];
    __shared__ float  kms[128];
    int b = blockIdx.y;
    int p0 = blockIdx.x * 128;
    int tid = threadIdx.x;
    const float invHW = 1.f / (float)HW;
    const float4* kvsrc = (const float4*)(g_kv + (long)b * 4096);
    for (int idx = tid; idx < 1024; idx += 256) {
        float4 v = kvsrc[idx];
        v.x *= invHW; v.y *= invHW; v.z *= invHW; v.w *= invHW;
        kvs4[idx] = v;
    }
    if (tid < 128) kms[tid] = g_ksum[b * 128 + tid] * invHW;
    __syncthreads();

    int h = tid >> 6, lp = tid & 63;
    int n1 = p0 + lp, n2 = p0 + 64 + lp;
    bool v1 = n1 < HW, v2 = n2 < HW;
    const float* qb = g_q + ((long)b * GC + h * 32) * HW;

    float q1[32], q2[32];
    #pragma unroll
    for (int d = 0; d < 32; d++) {
        q1[d] = v1 ? qb[(long)d * HW + n1] : 0.f;
        q2[d] = v2 ? qb[(long)d * HW + n2] : 0.f;
    }
    float s1 = 0.f, s2 = 0.f;
    #pragma unroll
    for (int d = 0; d < 32; d++) {
        float km = kms[h * 32 + d];
        s1 += q1[d] * km;
        s2 += q2[d] * km;
    }
    float z1 = 1.f / (s1 + 1e-6f);
    float z2 = 1.f / (s2 + 1e-6f);

    float* ob = out + FEATS_BASE + ((long)b * 384 + h * 32) * HW;
    #pragma unroll
    for (int e4 = 0; e4 < 8; e4++) {
        float4 a1 = make_float4(0,0,0,0), a2 = make_float4(0,0,0,0);
        #pragma unroll
        for (int d = 0; d < 32; d++) {
            float4 kv = kvs4[(h * 32 + d) * 8 + e4];
            a1.x += q1[d] * kv.x; a1.y += q1[d] * kv.y;
            a1.z += q1[d] * kv.z; a1.w += q1[d] * kv.w;
            a2.x += q2[d] * kv.x; a2.y += q2[d] * kv.y;
            a2.z += q2[d] * kv.z; a2.w += q2[d] * kv.w;
        }
        int e = e4 * 4;
        if (v1) {
            ob[(long)(e+0) * HW + n1] = a1.x * z1;
            ob[(long)(e+1) * HW + n1] = a1.y * z1;
            ob[(long)(e+2) * HW + n1] = a1.z * z1;
            ob[(long)(e+3) * HW + n1] = a1.w * z1;
        }
        if (v2) {
            ob[(long)(e+0) * HW + n2] = a2.x * z2;
            ob[(long)(e+1) * HW + n2] = a2.y * z2;
            ob[(long)(e+2) * HW + n2] = a2.z * z2;
            ob[(long)(e+3) * HW + n2] = a2.w * z2;
        }
    }
}

// ---------------------------------------------------------------------------
__global__ __launch_bounds__(112) void dw3_kernel(const float* __restrict__ x,
                                                  const float* __restrict__ w,
                                                  const float* __restrict__ bias,
                                                  float* __restrict__ out) {
    __shared__ float tile[10][60];
    __shared__ float ws[9];
    int y0 = blockIdx.x * 8;
    int c = blockIdx.y, b = blockIdx.z;
    int tid = threadIdx.x;
    const float* in = x + ((long)b * CT + 2 * GC + c) * HW;

    if (tid < 9) ws[tid] = w[c * 9 + tid];
    for (int idx = tid; idx < 10 * 58; idx += 112) {
        int r = idx / 58, cc = idx % 58;
        int iy = y0 - 1 + r, ix = cc - 1;
        tile[r][cc] = (iy >= 0 && iy < H_ && ix >= 0 && ix < W_) ? in[iy * W_ + ix] : 0.f;
    }
    __syncthreads();

    int gx = tid % 14, gy = tid / 14;
    int xb = gx * 4;
    float bb = bias[c];
    float a0 = bb, a1 = bb, a2 = bb, a3 = bb;
    #pragma unroll
    for (int ky = 0; ky < 3; ky++) {
        const float* row = &tile[gy + ky][xb];
        float r[6];
        #pragma unroll
        for (int i = 0; i < 6; i++) r[i] = row[i];
        #pragma unroll
        for (int kx = 0; kx < 3; kx++) {
            float wv = ws[ky * 3 + kx];
            a0 += wv * r[kx + 0];
            a1 += wv * r[kx + 1];
            a2 += wv * r[kx + 2];
            a3 += wv * r[kx + 3];
        }
    }
    float* ob = out + FEATS_BASE + ((long)b * 384 + GC + c) * HW + (y0 + gy) * W_ + xb;
    ob[0] = a0; ob[1] = a1; ob[2] = a2; ob[3] = a3;
}

// ---------------------------------------------------------------------------
__global__ __launch_bounds__(112) void dw7_kernel(const float* __restrict__ x,
                                                  const float* __restrict__ w,
                                                  const float* __restrict__ bias,
                                                  float* __restrict__ out) {
    __shared__ float tile[14][64];
    __shared__ float ws[49];
    int y0 = blockIdx.x * 8;
    int c = blockIdx.y, b = blockIdx.z;
    int tid = threadIdx.x;
    const float* in = x + ((long)b * CT + 3 * GC + c) * HW;

    if (tid < 49) ws[tid] = w[c * 49 + tid];
    for (int idx = tid; idx < 14 * 62; idx += 112) {
        int r = idx / 62, cc = idx % 62;
        int iy = y0 - 3 + r, ix = cc - 3;
        tile[r][cc] = (iy >= 0 && iy < H_ && ix >= 0 && ix < W_) ? in[iy * W_ + ix] : 0.f;
    }
    __syncthreads();

    int gx = tid % 14, gy = tid / 14;
    int xb = gx * 4;
    float bb = bias[c];
    float a0 = bb, a1 = bb, a2 = bb, a3 = bb;
    #pragma unroll
    for (int ky = 0; ky < 7; ky++) {
        const float* row = &tile[gy + ky][xb];
        float r[10];
        #pragma unroll
        for (int i = 0; i < 10; i++) r[i] = row[i];
        #pragma unroll
        for (int kx = 0; kx < 7; kx++) {
            float wv = ws[ky * 7 + kx];
            a0 += wv * r[kx + 0];
            a1 += wv * r[kx + 1];
            a2 += wv * r[kx + 2];
            a3 += wv * r[kx + 3];
        }
    }
    float* ob = out + FEATS_BASE + ((long)b * 384 + 2 * GC + c) * HW + (y0 + gy) * W_ + xb;
    ob[0] = a0; ob[1] = a1; ob[2] = a2; ob[3] = a3;
}

// ---------------------------------------------------------------------------
extern "C" void kernel_launch(void* const* d_in, const int* in_sizes, int n_in,
                              void* d_out, int out_size) {
    const float* x     = (const float*)d_in[0];
    const float* w_dw1 = (const float*)d_in[1];
    const float* b_dw1 = (const float*)d_in[2];
    const float* w_dw2 = (const float*)d_in[3];
    const float* b_dw2 = (const float*)d_in[4];
    const float* w_qk  = (const float*)d_in[5];
    const float* b_qk  = (const float*)d_in[6];
    float* out = (float*)d_out;

    cudaFuncSetAttribute(qk_mma_kernel, cudaFuncAttributeMaxDynamicSharedMemorySize, SM_TOTAL);

    // qk_mma (with fused kv/ksum) at launch index 3 for ncu window.
    prep_kernel<<<512, 256>>>(w_qk);
    copy_mem_kernel<<<(B_ * GC * HW / 4 + 255) / 256, 256>>>((const float4*)x, (float4*)out);
    cvt_kernel<<<dim3(98, 4, B_), 256>>>(x);
    qk_mma_kernel<<<dim3(25, 2, B_), 256, SM_TOTAL>>>(x, b_qk);
    att_kernel<<<dim3(25, B_), 256>>>(out);
    dw3_kernel<<<dim3(7, GC, B_), 112>>>(x, w_dw1, b_dw1, out);
    dw7_kernel<<<dim3(7, GC, B_), 112>>>(x, w_dw2, b_dw2, out);
}